// round 1
// baseline (speedup 1.0000x reference)
#include <cuda_runtime.h>
#include <math.h>

// MoEGate: x[16384,2048] @ W^T[2048,64] -> softmax -> top2 (+norm) -> seq aux loss
// Output layout (float32): [ indices(16384*2) | weights(16384*2) | aux_loss(1) ]

#define D_DIM   2048
#define E_EXP   64
#define TM      128          // tokens per block
#define KC      32           // K chunk
#define NTHREADS 128
#define NTOK    16384
#define NBLK    (NTOK / TM)  // 128
#define NCHUNK  (D_DIM / KC) // 64
#define SEQ     4096
#define BATCH   4
#define TILES_PER_B (NBLK / BATCH) // 32
#define ALPHA   0.01f

typedef unsigned long long u64;

// Deterministic scratch for aux loss (every slot rewritten every launch)
__device__ float g_scores_part[NBLK][E_EXP];
__device__ int   g_cnt_part[NBLK][E_EXP];

__device__ __forceinline__ void ffma2(u64& d, u64 a, u64 b) {
    asm volatile("fma.rn.f32x2 %0, %1, %2, %0;" : "+l"(d) : "l"(a), "l"(b));
}
__device__ __forceinline__ u64 bcast2(float x) {
    u64 r; unsigned xi = __float_as_uint(x);
    asm("mov.b64 %0, {%1, %1};" : "=l"(r) : "r"(xi));
    return r;
}
__device__ __forceinline__ void unpack2(u64 v, float& lo, float& hi) {
    unsigned a, b;
    asm("mov.b64 {%0, %1}, %2;" : "=r"(a), "=r"(b) : "l"(v));
    lo = __uint_as_float(a); hi = __uint_as_float(b);
}

struct P1 { float xs[KC][TM]; float ws[KC][E_EXP]; };           // 24576 B
struct P2 { float lg[TM][E_EXP + 1]; int cnt[E_EXP]; };         // 33536 B
union SmU { P1 p1; P2 p2; };

__global__ void __launch_bounds__(NTHREADS, 1)
moe_gate_kernel(const float* __restrict__ x, const float* __restrict__ w,
                float* __restrict__ out)
{
    __shared__ __align__(16) SmU sm;
    const int tid  = threadIdx.x;
    const int blk  = blockIdx.x;
    const int ex_g = tid & 7;   // experts ex_g*8 .. ex_g*8+7
    const int tp_g = tid >> 3;  // tokens  tp_g*8 .. tp_g*8+7 (as 4 f32x2 pairs)
    const int tok0 = blk * TM;

    u64 acc[8][4];
    #pragma unroll
    for (int j = 0; j < 8; j++)
        #pragma unroll
        for (int p = 0; p < 4; p++) acc[j][p] = 0ull;

    float4 xr[8], wr[4];

    // ---- load chunk 0 into staging registers ----
    #pragma unroll
    for (int i = 0; i < 8; i++) {
        int idx = i * NTHREADS + tid;
        int t = idx >> 3, f = idx & 7;
        xr[i] = *(const float4*)(x + (size_t)(tok0 + t) * D_DIM + f * 4);
    }
    #pragma unroll
    for (int i = 0; i < 4; i++) {
        int idx = i * NTHREADS + tid;
        int e = idx >> 3, f = idx & 7;
        wr[i] = *(const float4*)(w + (size_t)e * D_DIM + f * 4);
    }

    for (int c = 0; c < NCHUNK; c++) {
        __syncthreads();  // prior chunk's smem reads complete
        // ---- commit staged chunk to smem (x transposed to [k][tok]) ----
        #pragma unroll
        for (int i = 0; i < 8; i++) {
            int idx = i * NTHREADS + tid;
            int t = idx >> 3, f = idx & 7;
            sm.p1.xs[f * 4 + 0][t] = xr[i].x;
            sm.p1.xs[f * 4 + 1][t] = xr[i].y;
            sm.p1.xs[f * 4 + 2][t] = xr[i].z;
            sm.p1.xs[f * 4 + 3][t] = xr[i].w;
        }
        #pragma unroll
        for (int i = 0; i < 4; i++) {
            int idx = i * NTHREADS + tid;
            int e = idx >> 3, f = idx & 7;
            sm.p1.ws[f * 4 + 0][e] = wr[i].x;
            sm.p1.ws[f * 4 + 1][e] = wr[i].y;
            sm.p1.ws[f * 4 + 2][e] = wr[i].z;
            sm.p1.ws[f * 4 + 3][e] = wr[i].w;
        }
        __syncthreads();

        // ---- prefetch next chunk (LDGs issued; latency hidden by compute) ----
        if (c + 1 < NCHUNK) {
            const int ko = (c + 1) * KC;
            #pragma unroll
            for (int i = 0; i < 8; i++) {
                int idx = i * NTHREADS + tid;
                int t = idx >> 3, f = idx & 7;
                xr[i] = *(const float4*)(x + (size_t)(tok0 + t) * D_DIM + ko + f * 4);
            }
            #pragma unroll
            for (int i = 0; i < 4; i++) {
                int idx = i * NTHREADS + tid;
                int e = idx >> 3, f = idx & 7;
                wr[i] = *(const float4*)(w + (size_t)e * D_DIM + ko + f * 4);
            }
        }

        // ---- compute: 8 tok x 8 exp per thread, tokens f32x2-paired ----
        #pragma unroll 4
        for (int k = 0; k < KC; k++) {
            u64 xv[4];
            #pragma unroll
            for (int p = 0; p < 4; p++)
                xv[p] = *(const u64*)&sm.p1.xs[k][tp_g * 8 + 2 * p];
            #pragma unroll
            for (int j = 0; j < 8; j++) {
                u64 wb = bcast2(sm.p1.ws[k][ex_g * 8 + j]);
                #pragma unroll
                for (int p = 0; p < 4; p++) ffma2(acc[j][p], xv[p], wb);
            }
        }
    }

    __syncthreads();  // done reading p1 smem; safe to overwrite as p2

    // ---- spill logits to smem ----
    #pragma unroll
    for (int j = 0; j < 8; j++)
        #pragma unroll
        for (int p = 0; p < 4; p++) {
            float lo, hi; unpack2(acc[j][p], lo, hi);
            int t = tp_g * 8 + 2 * p;
            int e = ex_g * 8 + j;
            sm.p2.lg[t + 0][e] = lo;
            sm.p2.lg[t + 1][e] = hi;
        }
    if (tid < E_EXP) sm.p2.cnt[tid] = 0;
    __syncthreads();

    // ---- per-token softmax + top2 + outputs (1 thread : 1 token) ----
    {
        float* row = sm.p2.lg[tid];
        float mx = row[0];
        #pragma unroll
        for (int e = 1; e < E_EXP; e++) mx = fmaxf(mx, row[e]);
        float Z = 0.f;
        #pragma unroll
        for (int e = 0; e < E_EXP; e++) { float ex = expf(row[e] - mx); row[e] = ex; Z += ex; }
        // scores (exact division, mirrors reference softmax)
        #pragma unroll
        for (int e = 0; e < E_EXP; e++) row[e] = row[e] / Z;
        // top2 on scores; strict '>' keeps lowest index on ties (jax.lax.top_k semantics)
        float v1 = -1.f, v2 = -1.f; int i1 = 0, i2 = 0;
        #pragma unroll
        for (int e = 0; e < E_EXP; e++) {
            float s = row[e];
            if (s > v1)      { v2 = v1; i2 = i1; v1 = s; i1 = e; }
            else if (s > v2) { v2 = s;  i2 = e; }
        }
        float denom = v1 + v2 + 1e-20f;
        float w1 = v1 / denom, w2 = v2 / denom;

        int gt = tok0 + tid;
        out[gt * 2 + 0] = (float)i1;
        out[gt * 2 + 1] = (float)i2;
        out[2 * NTOK + gt * 2 + 0] = w1;
        out[2 * NTOK + gt * 2 + 1] = w2;

        atomicAdd(&sm.p2.cnt[i1], 1);
        atomicAdd(&sm.p2.cnt[i2], 1);
    }
    __syncthreads();

    // ---- deterministic per-block partials for aux loss ----
    if (tid < E_EXP) {
        float s = 0.f;
        for (int t = 0; t < TM; t++) s += sm.p2.lg[t][tid];
        g_scores_part[blk][tid] = s;
        g_cnt_part[blk][tid]    = sm.p2.cnt[tid];
    }
}

__global__ void moe_finalize_kernel(float* __restrict__ out)
{
    __shared__ float contrib[BATCH][E_EXP];
    int e = threadIdx.x;
    if (e < E_EXP) {
        for (int b = 0; b < BATCH; b++) {
            int cnt = 0; float ss = 0.f;
            for (int t = 0; t < TILES_PER_B; t++) {
                cnt += g_cnt_part[b * TILES_PER_B + t][e];
                ss  += g_scores_part[b * TILES_PER_B + t][e];
            }
            float ce = (float)cnt * ((float)E_EXP / (float)(SEQ * 2)); // cnt / (S*K/E)
            float ms = ss / (float)SEQ;
            contrib[b][e] = ce * ms;
        }
    }
    __syncthreads();
    if (e == 0) {
        float loss = 0.f;
        for (int b = 0; b < BATCH; b++) {
            float r = 0.f;
            for (int ee = 0; ee < E_EXP; ee++) r += contrib[b][ee];
            loss += r;
        }
        out[4 * NTOK] = loss / (float)BATCH * ALPHA;
    }
}

extern "C" void kernel_launch(void* const* d_in, const int* in_sizes, int n_in,
                              void* d_out, int out_size)
{
    const float* x = (const float*)d_in[0];  // [4,4096,2048] fp32
    const float* w = (const float*)d_in[1];  // [64,2048] fp32
    float* out = (float*)d_out;
    moe_gate_kernel<<<NBLK, NTHREADS>>>(x, w, out);
    moe_finalize_kernel<<<1, E_EXP>>>(out);
}